// round 2
// baseline (speedup 1.0000x reference)
#include <cuda_runtime.h>
#include <cuda_bf16.h>
#include <stdint.h>

// ============================================================================
// BFP8 quantized 3x3 conv (stride 1, pad 1), fused im2col + bf16 mma.sync GEMM
//   inputs:  [32,128,56,56] f32   weight: [256,128,3,3] f32   bias: [256] f32
//   output:  [32,256,56,56] f32
//   GEMM: M=100352, N=256, K=1152 (64-wide blocks share a power-of-2 scale)
// NOTE: harness compiles at compute_100 (no 'a' suffix) -> tcgen05 unavailable.
//       Use portable ldmatrix + mma.sync (HMMA) path.
// ============================================================================

#define C_IN      128
#define C_OUT     256
#define HWDIM     56
#define IMG_PIX   3136
#define K_TOTAL   1152
#define TILE_M    128
#define TILE_N    128
#define CHUNK_K   128
#define NUM_CHUNK 9
#define NTHREADS  256
#define GRID_M    784

#define A_STRIDE  136                 // bf16 elems per SMEM row (128 + 8 pad)
#define A_STRIDE_B (A_STRIDE * 2)     // 272 bytes
#define SMEM_B_OFF (TILE_M * A_STRIDE_B)   // 34816
#define C_STRIDE  132                 // floats per col-row in epilogue staging
#define SMEM_TOTAL (2 * TILE_M * A_STRIDE_B)   // 69632 (C reuses: 128*132*4=67584)

__device__ __align__(16) __nv_bfloat16 g_wq[C_OUT * K_TOTAL];

// ---------------------------------------------------------------------------
__device__ __forceinline__ uint32_t cvta_smem(const void* p) {
    uint32_t a;
    asm("{ .reg .u64 t; cvta.to.shared.u64 t, %1; cvt.u32.u64 %0, t; }"
        : "=r"(a) : "l"(p));
    return a;
}

__device__ __forceinline__ void ldsm_x4(uint32_t* d, uint32_t addr) {
    asm volatile("ldmatrix.sync.aligned.m8n8.x4.shared.b16 {%0,%1,%2,%3}, [%4];"
                 : "=r"(d[0]), "=r"(d[1]), "=r"(d[2]), "=r"(d[3]) : "r"(addr));
}

__device__ __forceinline__ void mma_16816(float* c, const uint32_t* a,
                                          uint32_t b0, uint32_t b1) {
    asm volatile(
        "mma.sync.aligned.m16n8k16.row.col.f32.bf16.bf16.f32 "
        "{%0,%1,%2,%3}, {%4,%5,%6,%7}, {%8,%9}, {%0,%1,%2,%3};"
        : "+f"(c[0]), "+f"(c[1]), "+f"(c[2]), "+f"(c[3])
        : "r"(a[0]), "r"(a[1]), "r"(a[2]), "r"(a[3]), "r"(b0), "r"(b1));
}

// BFP quantize given exact power-of-2 scale/inv
__device__ __forceinline__ float bfpq(float x, float inv, float scale) {
    float q = rintf(x * inv);                 // round half-even, exact scaling
    q = fminf(fmaxf(q, -128.0f), 127.0f);
    return q * scale;
}

__device__ __forceinline__ int block_exp(float mx) {
    mx = fmaxf(mx, 1e-38f);
    return ((__float_as_int(mx) >> 23) & 255) - 127;
}

// ---------------------------------------------------------------------------
// Kernel 1: quantize weight [256,1152] -> bf16 g_wq. One warp per (row, blk64).
// ---------------------------------------------------------------------------
__global__ void quant_w_kernel(const float* __restrict__ w) {
    int row = blockIdx.y, blk = blockIdx.x, lane = threadIdx.x;
    int base = row * K_TOTAL + blk * 64;

    float a = w[base + lane];
    float b = w[base + 32 + lane];
    float mx = fmaxf(fabsf(a), fabsf(b));
#pragma unroll
    for (int o = 16; o > 0; o >>= 1)
        mx = fmaxf(mx, __shfl_xor_sync(0xFFFFFFFFu, mx, o));

    int e = block_exp(mx);
    float scale = ldexpf(1.0f, e - 6);
    float inv   = ldexpf(1.0f, 6 - e);
    g_wq[base + lane]      = __float2bfloat16(bfpq(a, inv, scale));
    g_wq[base + 32 + lane] = __float2bfloat16(bfpq(b, inv, scale));
}

// ---------------------------------------------------------------------------
// Kernel 2: fused im2col + BFP quantize + bf16 mma.sync GEMM + bias epilogue.
// Grid (784, 2). 256 threads = 8 warps, warp tile 32x64.
// ---------------------------------------------------------------------------
__global__ __launch_bounds__(NTHREADS, 2)
void conv_bfp_kernel(const float* __restrict__ inp,
                     const float* __restrict__ bias,
                     float* __restrict__ out) {
    extern __shared__ __align__(16) char smem[];
    __nv_bfloat16* sA = reinterpret_cast<__nv_bfloat16*>(smem);
    __nv_bfloat16* sB = reinterpret_cast<__nv_bfloat16*>(smem + SMEM_B_OFF);
    float*         sC = reinterpret_cast<float*>(smem);

    const int tid  = threadIdx.x;
    const int wid  = tid >> 5;
    const int lane = tid & 31;
    const int warp_m = wid & 3;        // 4 warps along M
    const int warp_n = wid >> 2;       // 2 warps along N

    const int m_base = blockIdx.x * TILE_M;
    const int ntile  = blockIdx.y;

    // ---- A-production identity: thread owns (row r, 64-block hb) ----
    const int r  = tid & 127;
    const int hb = tid >> 7;
    const int m  = m_base + r;
    const int ni = m / IMG_PIX;
    const int p  = m - ni * IMG_PIX;
    const int ho = p / HWDIM;
    const int wo = p - ho * HWDIM;
    const float* img = inp + (size_t)ni * C_IN * IMG_PIX;

    // ---- ldmatrix lane base addresses ----
    // A frag (m16k16): rows lane&15, k-offset (lane>>4)*8
    const uint32_t aAddr0 = cvta_smem(sA)
        + (uint32_t)((warp_m * 32 + (lane & 15)) * A_STRIDE_B + (lane >> 4) * 16);
    // B frag pair (two n8 tiles): n-off (lane>>4)*8 + (lane&7), k-off ((lane>>3)&1)*8
    const uint32_t bAddr0 = cvta_smem(sB)
        + (uint32_t)((warp_n * 64 + ((lane >> 4) * 8) + (lane & 7)) * A_STRIDE_B
                     + ((lane >> 3) & 1) * 16);

    float acc[16][4];
#pragma unroll
    for (int i = 0; i < 16; ++i)
#pragma unroll
        for (int j = 0; j < 4; ++j) acc[i][j] = 0.0f;

    for (int kc = 0; kc < NUM_CHUNK; ++kc) {
        // ================= produce A chunk (quantized bf16) =================
        const int k0 = kc * CHUNK_K + hb * 64;
        float scale, inv;
        {
            // pass 1: block max
            int c  = k0 / 9;
            int rem = k0 - c * 9;
            int ii = rem / 3, jj = rem - ii * 3;
            const float* pimg = img + (size_t)c * IMG_PIX;
            float mx = 0.0f;
#pragma unroll
            for (int t = 0; t < 64; ++t) {
                int h = ho + ii - 1, w = wo + jj - 1;
                if ((unsigned)h < (unsigned)HWDIM && (unsigned)w < (unsigned)HWDIM)
                    mx = fmaxf(mx, fabsf(__ldg(pimg + h * HWDIM + w)));
                if (++jj == 3) { jj = 0; if (++ii == 3) { ii = 0; pimg += IMG_PIX; } }
            }
            int e = block_exp(mx);
            scale = ldexpf(1.0f, e - 6);
            inv   = ldexpf(1.0f, 6 - e);
        }
        {
            // pass 2: reload (L1-hot), quantize, store bf16x2
            int c  = k0 / 9;
            int rem = k0 - c * 9;
            int ii = rem / 3, jj = rem - ii * 3;
            const float* pimg = img + (size_t)c * IMG_PIX;
            uint32_t* dst = reinterpret_cast<uint32_t*>(
                reinterpret_cast<char*>(sA) + r * A_STRIDE_B + hb * 128);
#pragma unroll
            for (int t = 0; t < 64; t += 2) {
                float v0 = 0.0f, v1 = 0.0f;
                {
                    int h = ho + ii - 1, w = wo + jj - 1;
                    if ((unsigned)h < (unsigned)HWDIM && (unsigned)w < (unsigned)HWDIM)
                        v0 = __ldg(pimg + h * HWDIM + w);
                    if (++jj == 3) { jj = 0; if (++ii == 3) { ii = 0; pimg += IMG_PIX; } }
                }
                {
                    int h = ho + ii - 1, w = wo + jj - 1;
                    if ((unsigned)h < (unsigned)HWDIM && (unsigned)w < (unsigned)HWDIM)
                        v1 = __ldg(pimg + h * HWDIM + w);
                    if (++jj == 3) { jj = 0; if (++ii == 3) { ii = 0; pimg += IMG_PIX; } }
                }
                __nv_bfloat162 pr = __floats2bfloat162_rn(bfpq(v0, inv, scale),
                                                          bfpq(v1, inv, scale));
                dst[t >> 1] = *reinterpret_cast<uint32_t*>(&pr);
            }
        }

        // ================= load B chunk [128co x 128k] =================
        {
            const __nv_bfloat16* wq =
                g_wq + (size_t)(ntile * 128) * K_TOTAL + kc * CHUNK_K;
            const int row0 = tid >> 4, seg = tid & 15;
#pragma unroll
            for (int it = 0; it < 8; ++it) {
                int row = row0 + it * 16;
                uint4 v = *reinterpret_cast<const uint4*>(
                    wq + (size_t)row * K_TOTAL + seg * 8);
                *reinterpret_cast<uint4*>(
                    reinterpret_cast<char*>(sB) + row * A_STRIDE_B + seg * 16) = v;
            }
        }
        __syncthreads();

        // ================= 8 k16-steps of ldmatrix + mma =================
#pragma unroll
        for (int ks = 0; ks < 8; ++ks) {
            uint32_t a[2][4];
            ldsm_x4(a[0], aAddr0 + ks * 32);
            ldsm_x4(a[1], aAddr0 + 16 * A_STRIDE_B + ks * 32);
            uint32_t b[4][4];
#pragma unroll
            for (int nt2 = 0; nt2 < 4; ++nt2)
                ldsm_x4(b[nt2], bAddr0 + nt2 * 16 * A_STRIDE_B + ks * 32);
#pragma unroll
            for (int mt = 0; mt < 2; ++mt)
#pragma unroll
                for (int nt = 0; nt < 8; ++nt)
                    mma_16816(acc[mt * 8 + nt], a[mt],
                              b[nt >> 1][(nt & 1) * 2],
                              b[nt >> 1][(nt & 1) * 2 + 1]);
        }
        __syncthreads();   // A/B free for next chunk
    }

    // ================= epilogue: transpose via SMEM, coalesced store ========
#pragma unroll
    for (int mt = 0; mt < 2; ++mt)
#pragma unroll
        for (int nt = 0; nt < 8; ++nt) {
            int rr = warp_m * 32 + mt * 16 + (lane >> 2);
            int cc = warp_n * 64 + nt * 8 + 2 * (lane & 3);
            float* f = acc[mt * 8 + nt];
            sC[cc * C_STRIDE + rr]           = f[0];
            sC[(cc + 1) * C_STRIDE + rr]     = f[1];
            sC[cc * C_STRIDE + rr + 8]       = f[2];
            sC[(cc + 1) * C_STRIDE + rr + 8] = f[3];
        }
    __syncthreads();

#pragma unroll 4
    for (int i = 0; i < 16; ++i) {
        int cl = wid + i * 8;                 // local col 0..127
        int co = ntile * 128 + cl;
        float bv = __ldg(bias + co);
#pragma unroll
        for (int j = 0; j < 4; ++j) {
            int rr = j * 32 + lane;
            int mm = m_base + rr;
            int ni2 = mm / IMG_PIX;
            int pp  = mm - ni2 * IMG_PIX;
            out[(size_t)ni2 * (C_OUT * IMG_PIX) + (size_t)co * IMG_PIX + pp] =
                sC[cl * C_STRIDE + rr] + bv;
        }
    }
}

// ---------------------------------------------------------------------------
extern "C" void kernel_launch(void* const* d_in, const int* in_sizes, int n_in,
                              void* d_out, int out_size) {
    (void)in_sizes; (void)n_in; (void)out_size;
    const float* inp  = (const float*)d_in[0];
    const float* w    = (const float*)d_in[1];
    const float* bias = (const float*)d_in[2];
    float* out = (float*)d_out;

    cudaFuncSetAttribute(conv_bfp_kernel,
                         cudaFuncAttributeMaxDynamicSharedMemorySize, SMEM_TOTAL);

    quant_w_kernel<<<dim3(18, 256, 1), 32>>>(w);
    conv_bfp_kernel<<<dim3(GRID_M, 2, 1), NTHREADS, SMEM_TOTAL>>>(inp, bias, out);
}

// round 3
// speedup vs baseline: 1.1651x; 1.1651x over previous
#include <cuda_runtime.h>
#include <cuda_bf16.h>
#include <stdint.h>

// ============================================================================
// BFP8 quantized 3x3 conv (stride 1, pad 1), fused im2col + bf16 mma.sync GEMM
//   GEMM: M=100352, N=256, K=1152 (64-wide K-blocks share a power-of-2 scale)
// Round 3: TILE_N=256 (A produced once), 512 thr, compile-time tap offsets,
//          cp.async double-buffered B, pipelined gather/quantize vs MMA.
// ============================================================================

#define C_IN      128
#define C_OUT     256
#define HWDIM     56
#define IMG_PIX   3136
#define K_TOTAL   1152
#define TILE_M    128
#define CHUNK_K   128
#define NUM_CHUNK 9
#define NTHREADS  512
#define GRID_M    784

// SMEM layout (bytes)
#define A_ROW_B   256                  // 128 bf16, XOR-swizzled units
#define B_ROW_B   272                  // 128 bf16 + 16B pad
#define SA_SZ     (TILE_M * A_ROW_B)   // 32768
#define SB_SZ     (C_OUT * B_ROW_B)    // 69632
#define SA_OFF    0                    // 2 buffers
#define SB_OFF    (2 * SA_SZ)          // 65536, 2 buffers
#define HM_OFF    (SB_OFF + 2 * SB_SZ) // 204800, 2 x 512 floats
#define SMEM_TOTAL (HM_OFF + 4096)     // 208896

#define C_STRIDE  132

__device__ __align__(16) __nv_bfloat16 g_wq[C_OUT * K_TOTAL];

// ---------------------------------------------------------------------------
__device__ __forceinline__ uint32_t cvta_smem(const void* p) {
    uint32_t a;
    asm("{ .reg .u64 t; cvta.to.shared.u64 t, %1; cvt.u32.u64 %0, t; }"
        : "=r"(a) : "l"(p));
    return a;
}

__device__ __forceinline__ void ldsm_x4(uint32_t* d, uint32_t addr) {
    asm volatile("ldmatrix.sync.aligned.m8n8.x4.shared.b16 {%0,%1,%2,%3}, [%4];"
                 : "=r"(d[0]), "=r"(d[1]), "=r"(d[2]), "=r"(d[3]) : "r"(addr));
}

__device__ __forceinline__ void mma_16816(float* c, const uint32_t* a,
                                          uint32_t b0, uint32_t b1) {
    asm volatile(
        "mma.sync.aligned.m16n8k16.row.col.f32.bf16.bf16.f32 "
        "{%0,%1,%2,%3}, {%4,%5,%6,%7}, {%8,%9}, {%0,%1,%2,%3};"
        : "+f"(c[0]), "+f"(c[1]), "+f"(c[2]), "+f"(c[3])
        : "r"(a[0]), "r"(a[1]), "r"(a[2]), "r"(a[3]), "r"(b0), "r"(b1));
}

__device__ __forceinline__ void cp_async16(uint32_t dst, const void* src) {
    asm volatile("cp.async.cg.shared.global [%0], [%1], 16;"
                 :: "r"(dst), "l"(src));
}
__device__ __forceinline__ void cp_commit() {
    asm volatile("cp.async.commit_group;");
}
template <int N>
__device__ __forceinline__ void cp_wait() {
    asm volatile("cp.async.wait_group %0;" :: "n"(N));
}

__device__ __forceinline__ float bfpq(float x, float inv, float scale) {
    float q = rintf(x * inv);
    q = fminf(fmaxf(q, -128.0f), 127.0f);
    return q * scale;
}
__device__ __forceinline__ int block_exp(float mx) {
    mx = fmaxf(mx, 1e-38f);
    return ((__float_as_int(mx) >> 23) & 255) - 127;
}

// ---------------------------------------------------------------------------
// Kernel 1: quantize weight -> bf16 g_wq
// ---------------------------------------------------------------------------
__global__ void quant_w_kernel(const float* __restrict__ w) {
    int row = blockIdx.y, blk = blockIdx.x, lane = threadIdx.x;
    int base = row * K_TOTAL + blk * 64;
    float a = w[base + lane];
    float b = w[base + 32 + lane];
    float mx = fmaxf(fabsf(a), fabsf(b));
#pragma unroll
    for (int o = 16; o > 0; o >>= 1)
        mx = fmaxf(mx, __shfl_xor_sync(0xFFFFFFFFu, mx, o));
    int e = block_exp(mx);
    float scale = __int_as_float((e + 121) << 23);
    float inv   = __int_as_float((133 - e) << 23);
    g_wq[base + lane]      = __float2bfloat16(bfpq(a, inv, scale));
    g_wq[base + 32 + lane] = __float2bfloat16(bfpq(b, inv, scale));
}

// ---------------------------------------------------------------------------
// Kernel 2: fused conv. Grid 784 CTAs, 512 threads (16 warps, 4x4 warp grid).
// ---------------------------------------------------------------------------
__global__ __launch_bounds__(NTHREADS, 1)
void conv_bfp_kernel(const float* __restrict__ inp,
                     const float* __restrict__ bias,
                     float* __restrict__ out) {
    extern __shared__ __align__(16) char smem[];
    const uint32_t smem_u = cvta_smem(smem);
    float* hmax = reinterpret_cast<float*>(smem + HM_OFF);

    const int tid  = threadIdx.x;
    const int wid  = tid >> 5;
    const int lane = tid & 31;
    const int warp_m = wid & 3;
    const int warp_n = wid >> 2;

    const int m_base = blockIdx.x * TILE_M;

    // ---- producer identity: thread owns (row r, 32-wide sub-block q) ----
    const int r    = tid & 127;
    const int q    = tid >> 7;          // 0..3, koff = q*32
    const int koff = q * 32;
    {
        // nothing
    }
    const int m  = m_base + r;
    const int ni = m / IMG_PIX;
    const int p  = m - ni * IMG_PIX;
    const int ho = p / HWDIM;
    const int wo = p - ho * HWDIM;
    // base pointer at (ho-1, wo-1); taps add kh*56+kw (compile-time)
    const float* pix = inp + (size_t)ni * C_IN * IMG_PIX + (ho * HWDIM + wo) - 57;

    uint32_t vmask = 0;
#pragma unroll
    for (int kh = 0; kh < 3; ++kh)
#pragma unroll
        for (int kw = 0; kw < 3; ++kw) {
            int h = ho + kh - 1, w = wo + kw - 1;
            if ((unsigned)h < (unsigned)HWDIM && (unsigned)w < (unsigned)HWDIM)
                vmask |= 1u << (kh * 3 + kw);
        }

    // ---- A-tile STS constants (row r, XOR swizzle by r&15 on 16B units) ----
    const uint32_t xsh  = (uint32_t)(r & 15) << 4;
    const uint32_t arow_sts = (uint32_t)r * A_ROW_B;

    // ---- ldmatrix bases ----
    const int arow = warp_m * 32 + (lane & 15);
    const uint32_t ax   = (uint32_t)(arow & 15);
    const uint32_t ahi  = (uint32_t)(lane >> 4);
    const uint32_t abase_lane = smem_u + SA_OFF + (uint32_t)arow * A_ROW_B;
    const uint32_t bbase_lane = smem_u + SB_OFF
        + (uint32_t)(warp_n * 64 + ((lane >> 4) * 8) + (lane & 7)) * B_ROW_B
        + (uint32_t)((lane >> 3) & 1) * 16;

    float acc[16][4];
#pragma unroll
    for (int i = 0; i < 16; ++i)
#pragma unroll
        for (int j = 0; j < 4; ++j) acc[i][j] = 0.0f;

    // ---- helpers as lambdas ----
    auto loadB = [&](int kc, int buf) {
        const __nv_bfloat16* src = g_wq + (size_t)(tid >> 1) * K_TOTAL
                                   + kc * CHUNK_K + (tid & 1) * 64;
        uint32_t dst = smem_u + SB_OFF + buf * SB_SZ
                     + (uint32_t)(tid >> 1) * B_ROW_B + (tid & 1) * 128;
#pragma unroll
        for (int i = 0; i < 8; ++i)
            cp_async16(dst + i * 16, src + i * 8);
        cp_commit();
    };

    auto gmax = [&](int kc) -> float {
        int k0 = kc * CHUNK_K + koff;
        int c0 = k0 / 9;
        int tap0 = k0 - c0 * 9;
        const float* pb = pix + (size_t)c0 * IMG_PIX;
        float mx = 0.0f;
#pragma unroll
        for (int ci = 0; ci < 5; ++ci)
#pragma unroll
            for (int tap = 0; tap < 9; ++tap) {
                const int u = ci * 9 + tap;
                const int off = ci * IMG_PIX + (tap / 3) * HWDIM + (tap % 3);
                if ((unsigned)(u - tap0) < 32u) {
                    float v = ((vmask >> tap) & 1u) ? __ldg(pb + off) : 0.0f;
                    mx = fmaxf(mx, fabsf(v));
                }
            }
        return mx;
    };

    auto qpass = [&](int kc, float mx, int buf) {
        int k0 = kc * CHUNK_K + koff;
        int c0 = k0 / 9;
        int tap0 = k0 - c0 * 9;
        const float* pb = pix + (size_t)c0 * IMG_PIX;
        int e = block_exp(mx);
        float scale = __int_as_float((e + 121) << 23);
        float inv   = __int_as_float((133 - e) << 23);
        char* rowb = smem + SA_OFF + buf * SA_SZ + arow_sts;
        int cb2 = 2 * (koff - tap0);
#pragma unroll
        for (int ci = 0; ci < 5; ++ci)
#pragma unroll
            for (int tap = 0; tap < 9; ++tap) {
                const int u = ci * 9 + tap;
                const int off = ci * IMG_PIX + (tap / 3) * HWDIM + (tap % 3);
                if ((unsigned)(u - tap0) < 32u) {
                    float v = ((vmask >> tap) & 1u) ? __ldg(pb + off) : 0.0f;
                    float qv = bfpq(v, inv, scale);
                    uint16_t hv;
                    __nv_bfloat16 bh = __float2bfloat16(qv);
                    hv = *reinterpret_cast<uint16_t*>(&bh);
                    uint32_t a = (uint32_t)(cb2 + 2 * u) ^ xsh;
                    *reinterpret_cast<uint16_t*>(rowb + a) = hv;
                }
            }
    };

    auto domma = [&](int buf) {
        const uint32_t abase = abase_lane + buf * SA_SZ;
        const uint32_t bbase = bbase_lane + buf * SB_SZ;
#pragma unroll
        for (int ks = 0; ks < 8; ++ks) {
            uint32_t unit = ((uint32_t)(2 * ks) + ahi) ^ ax;
            uint32_t a0[4], a1[4];
            ldsm_x4(a0, abase + (unit << 4));
            ldsm_x4(a1, abase + 16 * A_ROW_B + (unit << 4));
            uint32_t b[4][4];
#pragma unroll
            for (int nt2 = 0; nt2 < 4; ++nt2)
                ldsm_x4(b[nt2], bbase + nt2 * 16 * B_ROW_B + ks * 32);
#pragma unroll
            for (int nt = 0; nt < 8; ++nt) {
                mma_16816(acc[nt],     a0, b[nt >> 1][(nt & 1) * 2],
                                           b[nt >> 1][(nt & 1) * 2 + 1]);
                mma_16816(acc[8 + nt], a1, b[nt >> 1][(nt & 1) * 2],
                                           b[nt >> 1][(nt & 1) * 2 + 1]);
            }
        }
    };

    // =========================== pipeline ===================================
    loadB(0, 0);
    {
        float mx = gmax(0);
        hmax[tid] = mx;
    }
    __syncthreads();
    {
        float m2 = fmaxf(hmax[tid], hmax[tid ^ 128]);
        qpass(0, m2, 0);
    }

    for (int kc = 0; kc < NUM_CHUNK; ++kc) {
        const int cur = kc & 1, nxt = cur ^ 1;
        if (kc < NUM_CHUNK - 1) {
            loadB(kc + 1, nxt);
            float mx = gmax(kc + 1);
            hmax[nxt * 512 + tid] = mx;
        }
        if (kc < NUM_CHUNK - 1) cp_wait<1>(); else cp_wait<0>();
        __syncthreads();               // A[cur], B[cur], hmax[nxt] visible

        domma(cur);

        if (kc < NUM_CHUNK - 1) {
            float m2 = fmaxf(hmax[nxt * 512 + tid], hmax[nxt * 512 + (tid ^ 128)]);
            qpass(kc + 1, m2, nxt);
        }
        __syncthreads();               // MMA done; buffers reusable
    }

    // =========================== epilogue ===================================
    float* sC = reinterpret_cast<float*>(smem);
#pragma unroll
    for (int mt = 0; mt < 2; ++mt)
#pragma unroll
        for (int nt = 0; nt < 8; ++nt) {
            int rr = warp_m * 32 + mt * 16 + (lane >> 2);
            int cc = warp_n * 64 + nt * 8 + 2 * (lane & 3);
            float* f = acc[mt * 8 + nt];
            sC[cc * C_STRIDE + rr]           = f[0];
            sC[(cc + 1) * C_STRIDE + rr]     = f[1];
            sC[cc * C_STRIDE + rr + 8]       = f[2];
            sC[(cc + 1) * C_STRIDE + rr + 8] = f[3];
        }
    __syncthreads();

#pragma unroll
    for (int j = 0; j < 4; ++j) {
        int rr = j * 32 + lane;
        int mm = m_base + rr;
        int ni2 = mm / IMG_PIX;
        int pp  = mm - ni2 * IMG_PIX;
        float* ob = out + (size_t)ni2 * (C_OUT * IMG_PIX) + pp;
#pragma unroll 4
        for (int i = 0; i < 16; ++i) {
            int cl = wid * 16 + i;
            ob[(size_t)cl * IMG_PIX] = sC[cl * C_STRIDE + rr] + __ldg(bias + cl);
        }
    }
}

// ---------------------------------------------------------------------------
extern "C" void kernel_launch(void* const* d_in, const int* in_sizes, int n_in,
                              void* d_out, int out_size) {
    (void)in_sizes; (void)n_in; (void)out_size;
    const float* inp  = (const float*)d_in[0];
    const float* w    = (const float*)d_in[1];
    const float* bias = (const float*)d_in[2];
    float* out = (float*)d_out;

    cudaFuncSetAttribute(conv_bfp_kernel,
                         cudaFuncAttributeMaxDynamicSharedMemorySize, SMEM_TOTAL);

    quant_w_kernel<<<dim3(18, 256, 1), 32>>>(w);
    conv_bfp_kernel<<<GRID_M, NTHREADS, SMEM_TOTAL>>>(inp, bias, out);
}

// round 4
// speedup vs baseline: 2.8824x; 2.4740x over previous
#include <cuda_runtime.h>
#include <cuda_bf16.h>
#include <stdint.h>

// ============================================================================
// BFP8 quantized 3x3 conv (stride 1, pad 1) == GEMM M=100352, N=256, K=1152
// Round 4: split into (K1) quantize-A -> bf16 scratch, (K2) clean pipelined
//          bf16 mma.sync GEMM. Decouples gather latency from tensor work.
// ============================================================================

#define C_IN      128
#define C_OUT     256
#define HWDIM     56
#define IMG_PIX   3136
#define K_TOTAL   1152
#define M_TOTAL   100352
#define GRID_M    784

__device__ __align__(16) __nv_bfloat16 g_wq[C_OUT * K_TOTAL];
__device__ __align__(16) __nv_bfloat16 g_qa[(size_t)M_TOTAL * K_TOTAL]; // 231 MB

// ---------------------------------------------------------------------------
__device__ __forceinline__ uint32_t cvta_smem(const void* p) {
    uint32_t a;
    asm("{ .reg .u64 t; cvta.to.shared.u64 t, %1; cvt.u32.u64 %0, t; }"
        : "=r"(a) : "l"(p));
    return a;
}
__device__ __forceinline__ void ldsm_x4(uint32_t* d, uint32_t addr) {
    asm volatile("ldmatrix.sync.aligned.m8n8.x4.shared.b16 {%0,%1,%2,%3}, [%4];"
                 : "=r"(d[0]), "=r"(d[1]), "=r"(d[2]), "=r"(d[3]) : "r"(addr));
}
__device__ __forceinline__ void mma_16816(float* c, const uint32_t* a,
                                          uint32_t b0, uint32_t b1) {
    asm volatile(
        "mma.sync.aligned.m16n8k16.row.col.f32.bf16.bf16.f32 "
        "{%0,%1,%2,%3}, {%4,%5,%6,%7}, {%8,%9}, {%0,%1,%2,%3};"
        : "+f"(c[0]), "+f"(c[1]), "+f"(c[2]), "+f"(c[3])
        : "r"(a[0]), "r"(a[1]), "r"(a[2]), "r"(a[3]), "r"(b0), "r"(b1));
}
__device__ __forceinline__ void cp_async16(uint32_t dst, const void* src) {
    asm volatile("cp.async.cg.shared.global [%0], [%1], 16;" :: "r"(dst), "l"(src));
}
__device__ __forceinline__ void cp_commit() {
    asm volatile("cp.async.commit_group;");
}
template <int N>
__device__ __forceinline__ void cp_wait() {
    asm volatile("cp.async.wait_group %0;" :: "n"(N));
}

__device__ __forceinline__ int block_exp(float mx) {
    mx = fmaxf(mx, 1e-38f);
    return ((__float_as_int(mx) >> 23) & 255) - 127;
}
// quantize given exact pow2 inv/scale; round>= -128 guaranteed, clamp top only
__device__ __forceinline__ float bfpq(float x, float inv, float scale) {
    float q = rintf(x * inv);
    q = fminf(q, 127.0f);
    return q * scale;
}

// ---------------------------------------------------------------------------
// Kernel 0: quantize weight -> bf16 g_wq
// ---------------------------------------------------------------------------
__global__ void quant_w_kernel(const float* __restrict__ w) {
    int row = blockIdx.y, blk = blockIdx.x, lane = threadIdx.x;
    int base = row * K_TOTAL + blk * 64;
    float a = w[base + lane];
    float b = w[base + 32 + lane];
    float mx = fmaxf(fabsf(a), fabsf(b));
#pragma unroll
    for (int o = 16; o > 0; o >>= 1)
        mx = fmaxf(mx, __shfl_xor_sync(0xFFFFFFFFu, mx, o));
    int e = block_exp(mx);
    float scale = __int_as_float((e + 121) << 23);
    float inv   = __int_as_float((133 - e) << 23);
    g_wq[base + lane]      = __float2bfloat16(bfpq(a, inv, scale));
    g_wq[base + 32 + lane] = __float2bfloat16(bfpq(b, inv, scale));
}

// ---------------------------------------------------------------------------
// Kernel 1: quantize im2col(A) -> g_qa  (grid 784 x 18, 256 threads)
// thread owns 32 consecutive k of one (row, 64-block); values in registers.
// ---------------------------------------------------------------------------
template <int S>
__device__ __forceinline__ void gather32(const float* __restrict__ pix,
                                         uint32_t vmask, float* v, float& mx) {
#pragma unroll
    for (int e = 0; e < 32; ++e) {
        const int u   = S + e;
        const int ci  = u / 9;
        const int tap = u % 9;
        const int off = ci * IMG_PIX + (tap / 3) * HWDIM + (tap % 3);
        float val = ((vmask >> tap) & 1u) ? __ldg(pix + off) : 0.0f;
        v[e] = val;
        mx = fmaxf(mx, fabsf(val));
    }
}

__global__ void quant_a_kernel(const float* __restrict__ inp) {
    __shared__ float smax[256];
    const int tid  = threadIdx.x;
    const int r    = tid & 127;
    const int half = tid >> 7;
    const int m  = blockIdx.x * 128 + r;
    const int b  = blockIdx.y;              // 64-block index 0..17
    const int t0 = b % 9;                   // (64*b) % 9
    const int c0 = (64 * b) / 9;

    const int ni = m / IMG_PIX;
    const int p  = m - ni * IMG_PIX;
    const int ho = p / HWDIM;
    const int wo = p - ho * HWDIM;
    const float* pix = inp + ((size_t)ni * C_IN + c0) * IMG_PIX
                       + ho * HWDIM + wo - 57;

    uint32_t vmask = 0;
#pragma unroll
    for (int kh = 0; kh < 3; ++kh)
#pragma unroll
        for (int kw = 0; kw < 3; ++kw) {
            int h = ho + kh - 1, w = wo + kw - 1;
            if ((unsigned)h < (unsigned)HWDIM && (unsigned)w < (unsigned)HWDIM)
                vmask |= 1u << (kh * 3 + kw);
        }

    float v[32];
    float mx = 0.0f;
    switch (t0) {
        case 0: if (half) gather32<32>(pix, vmask, v, mx); else gather32<0>(pix, vmask, v, mx); break;
        case 1: if (half) gather32<33>(pix, vmask, v, mx); else gather32<1>(pix, vmask, v, mx); break;
        case 2: if (half) gather32<34>(pix, vmask, v, mx); else gather32<2>(pix, vmask, v, mx); break;
        case 3: if (half) gather32<35>(pix, vmask, v, mx); else gather32<3>(pix, vmask, v, mx); break;
        case 4: if (half) gather32<36>(pix, vmask, v, mx); else gather32<4>(pix, vmask, v, mx); break;
        case 5: if (half) gather32<37>(pix, vmask, v, mx); else gather32<5>(pix, vmask, v, mx); break;
        case 6: if (half) gather32<38>(pix, vmask, v, mx); else gather32<6>(pix, vmask, v, mx); break;
        case 7: if (half) gather32<39>(pix, vmask, v, mx); else gather32<7>(pix, vmask, v, mx); break;
        default:if (half) gather32<40>(pix, vmask, v, mx); else gather32<8>(pix, vmask, v, mx); break;
    }

    smax[tid] = mx;
    __syncthreads();
    mx = fmaxf(mx, smax[tid ^ 128]);

    int e = block_exp(mx);
    float scale = __int_as_float((e + 121) << 23);
    float inv   = __int_as_float((133 - e) << 23);

    uint32_t pk[16];
#pragma unroll
    for (int i = 0; i < 16; ++i) {
        __nv_bfloat162 pr = __floats2bfloat162_rn(bfpq(v[2 * i],     inv, scale),
                                                  bfpq(v[2 * i + 1], inv, scale));
        pk[i] = *reinterpret_cast<uint32_t*>(&pr);
    }
    uint4* dst = reinterpret_cast<uint4*>(g_qa + (size_t)m * K_TOTAL
                                          + b * 64 + half * 32);
#pragma unroll
    for (int i = 0; i < 4; ++i)
        dst[i] = make_uint4(pk[4 * i], pk[4 * i + 1], pk[4 * i + 2], pk[4 * i + 3]);
}

// ---------------------------------------------------------------------------
// Kernel 2: bf16 GEMM  C[128x256 tile] = qA @ qW^T + bias, NCHW epilogue.
// 512 threads (16 warps, 4x4), warp tile 32x64, CHUNK_K=64, 4-stage cp.async.
// ---------------------------------------------------------------------------
#define K2_CHUNK   64
#define K2_NCHUNK  18
#define K2_STAGES  4
#define K2_A_SZ    16384              // 128 rows * 128B
#define K2_B_SZ    32768              // 256 rows * 128B
#define K2_STAGE   (K2_A_SZ + K2_B_SZ)
#define K2_SMEM    (K2_STAGES * K2_STAGE)   // 196608
#define C_STRIDE   132

__global__ __launch_bounds__(512, 1)
void gemm_kernel(const float* __restrict__ bias, float* __restrict__ out) {
    extern __shared__ __align__(16) char smem[];
    const uint32_t smem_u = cvta_smem(smem);

    const int tid  = threadIdx.x;
    const int wid  = tid >> 5;
    const int lane = tid & 31;
    const int warp_m = wid & 3;
    const int warp_n = wid >> 2;
    const int m_base = blockIdx.x * 128;

    // ---- cp.async load identities ----
    const int la_r = tid >> 3;          // A: rows tid>>3 and +64
    const int la_j = tid & 7;
    const uint32_t la_dst = (uint32_t)(la_r * 128 + ((la_j ^ (la_r & 7)) << 4));
    const uint32_t la_dst2 = (uint32_t)((la_r + 64) * 128
                                        + ((la_j ^ ((la_r + 64) & 7)) << 4));
    const __nv_bfloat16* a_src = g_qa + (size_t)(m_base + la_r) * K_TOTAL + la_j * 8;
    const __nv_bfloat16* a_src2 = a_src + (size_t)64 * K_TOTAL;

    auto load_stage = [&](int kc, int s) {
        uint32_t ab = smem_u + s * K2_STAGE;
        cp_async16(ab + la_dst,  a_src  + kc * K2_CHUNK);
        cp_async16(ab + la_dst2, a_src2 + kc * K2_CHUNK);
        uint32_t bb = ab + K2_A_SZ;
#pragma unroll
        for (int i = 0; i < 4; ++i) {
            int n = (tid + i * 512) >> 3;
            int j = tid & 7;
            cp_async16(bb + (uint32_t)(n * 128 + ((j ^ (n & 7)) << 4)),
                       g_wq + (size_t)n * K_TOTAL + kc * K2_CHUNK + j * 8);
        }
        cp_commit();
    };

    // ---- ldmatrix identities ----
    const int arow  = warp_m * 32 + (lane & 15);
    const uint32_t akey = (uint32_t)(arow & 7) << 4;
    const uint32_t abase = (uint32_t)(arow * 128);
    const uint32_t ahi  = (uint32_t)(lane >> 4) << 4;    // k-half unit *16

    const int nrow  = warp_n * 64 + ((lane >> 4) * 8) + (lane & 7);
    const uint32_t bkey = (uint32_t)(nrow & 7) << 4;
    const uint32_t bbase = (uint32_t)(K2_A_SZ + nrow * 128);
    const uint32_t bkub = (uint32_t)((lane >> 3) & 1) << 4;

    float acc[16][4];
#pragma unroll
    for (int i = 0; i < 16; ++i)
#pragma unroll
        for (int j = 0; j < 4; ++j) acc[i][j] = 0.0f;

    // ---- prologue: 3 stages in flight ----
    load_stage(0, 0);
    load_stage(1, 1);
    load_stage(2, 2);

    for (int kc = 0; kc < K2_NCHUNK; ++kc) {
        cp_wait<2>();
        __syncthreads();
        const uint32_t sb = smem_u + (kc & 3) * K2_STAGE;

#pragma unroll
        for (int ks = 0; ks < 4; ++ks) {
            uint32_t a0[4], a1[4];
            uint32_t au = (((uint32_t)(2 * ks) << 4) + ahi);
            ldsm_x4(a0, sb + abase + (au ^ akey));
            ldsm_x4(a1, sb + abase + 16 * 128 + (au ^ akey));
            uint32_t b[4][4];
            uint32_t bu = (((uint32_t)(2 * ks) << 4) + bkub) ^ bkey;
#pragma unroll
            for (int nt2 = 0; nt2 < 4; ++nt2)
                ldsm_x4(b[nt2], sb + bbase + nt2 * 16 * 128 + bu);
#pragma unroll
            for (int nt = 0; nt < 8; ++nt) {
                mma_16816(acc[nt],     a0, b[nt >> 1][(nt & 1) * 2],
                                           b[nt >> 1][(nt & 1) * 2 + 1]);
                mma_16816(acc[8 + nt], a1, b[nt >> 1][(nt & 1) * 2],
                                           b[nt >> 1][(nt & 1) * 2 + 1]);
            }
        }
        __syncthreads();
        if (kc + 3 < K2_NCHUNK) load_stage(kc + 3, (kc + 3) & 3);
        else cp_commit();            // keep wait_group count consistent
    }

    // ---- epilogue: transpose via SMEM, coalesced NCHW stores + bias ----
    __syncthreads();
    float* sC = reinterpret_cast<float*>(smem);
#pragma unroll
    for (int mt = 0; mt < 2; ++mt)
#pragma unroll
        for (int nt = 0; nt < 8; ++nt) {
            int rr = warp_m * 32 + mt * 16 + (lane >> 2);
            int cc = warp_n * 64 + nt * 8 + 2 * (lane & 3);
            float* f = acc[mt * 8 + nt];
            sC[cc * C_STRIDE + rr]           = f[0];
            sC[(cc + 1) * C_STRIDE + rr]     = f[1];
            sC[cc * C_STRIDE + rr + 8]       = f[2];
            sC[(cc + 1) * C_STRIDE + rr + 8] = f[3];
        }
    __syncthreads();

#pragma unroll
    for (int j = 0; j < 4; ++j) {
        int rr = j * 32 + lane;
        int mm = m_base + rr;
        int ni2 = mm / IMG_PIX;
        int pp  = mm - ni2 * IMG_PIX;
        float* ob = out + (size_t)ni2 * (C_OUT * IMG_PIX) + pp;
#pragma unroll 4
        for (int i = 0; i < 16; ++i) {
            int cl = wid * 16 + i;
            ob[(size_t)cl * IMG_PIX] = sC[cl * C_STRIDE + rr] + __ldg(bias + cl);
        }
    }
}

// ---------------------------------------------------------------------------
extern "C" void kernel_launch(void* const* d_in, const int* in_sizes, int n_in,
                              void* d_out, int out_size) {
    (void)in_sizes; (void)n_in; (void)out_size;
    const float* inp  = (const float*)d_in[0];
    const float* w    = (const float*)d_in[1];
    const float* bias = (const float*)d_in[2];
    float* out = (float*)d_out;

    cudaFuncSetAttribute(gemm_kernel,
                         cudaFuncAttributeMaxDynamicSharedMemorySize, K2_SMEM);

    quant_w_kernel<<<dim3(18, 256, 1), 32>>>(w);
    quant_a_kernel<<<dim3(GRID_M, 18, 1), 256>>>(inp);
    gemm_kernel<<<GRID_M, 512, K2_SMEM>>>(bias, out);
}